// round 2
// baseline (speedup 1.0000x reference)
#include <cuda_runtime.h>

// ---------------------------------------------------------------------------
// Bayes_4294967296643 : full pipeline
// inputs: feats(4,256,64,64) K Q same, w_gap(20,256), w_gap_r(20,256),
//         conv_w(256,512,3,3), conv_b(256), label(4) int32
// output: nxt(4,256,64,64) ++ pred(4,20) ++ pred_r(4,20)   (f32)
// ---------------------------------------------------------------------------

#define NB    4
#define CH    256
#define HW    4096
#define LPIX  16384
#define NCLS  20

typedef unsigned long long ull;

// ---- scratch (device globals; no allocation allowed) ----------------------
__device__ float g_m[NB*HW];          // relu'd label heatmap (mask numerator)
__device__ float g_rmax[64];          // per-block max partials
__device__ float g_scale[NB];         // 1/max(1, max)
__device__ float g_chansum[NB*CH];    // per-(n,c) pixel sums of feats
__device__ float g_S[NB*CH];          // per-(n,c) sums of feats*wsum
__device__ float g_atti[4*25*LPIX];   // infusion attention  [a][k][p]
__device__ float g_attd[4*9*LPIX];    // diffusion attention [a][k][p]
__device__ float g_wsum[4*LPIX];      // scatter-weight sums [a][p]
__device__ float g_wT[3*512*3*256];   // weights transposed [kh][ci][kw][co]
__device__ float g_x[NB*512*HW];      // conv input (feats*mask ++ feats_d)

// ---- f32x2 packed helpers -------------------------------------------------
__device__ __forceinline__ ull pk2(float x, float y){
    ull r; asm("mov.b64 %0, {%1,%2};" : "=l"(r) : "f"(x), "f"(y)); return r;
}
__device__ __forceinline__ void upk2(ull v, float& lo, float& hi){
    asm("mov.b64 {%0,%1}, %2;" : "=f"(lo), "=f"(hi) : "l"(v));
}
__device__ __forceinline__ void ffma2(ull& d, ull a, ull b){
    asm("fma.rn.f32x2 %0, %1, %2, %3;" : "=l"(d) : "l"(a), "l"(b), "l"(d));
}

// ---------------------------------------------------------------------------
// 1) mask numerator (label-channel heatmap, relu'd) + per-block max
//    grid 64 x 256 : one thread per pixel
// ---------------------------------------------------------------------------
__global__ void k_mask(const float* __restrict__ feats,
                       const float* __restrict__ wgap,
                       const int*   __restrict__ label){
    int t = threadIdx.x;
    int p = blockIdx.x*256 + t;
    int n = p >> 12, hw = p & 4095;
    int lab = label[n];
    const float* f  = feats + (size_t)n*CH*HW + hw;
    const float* wg = wgap + lab*CH;
    float s = 0.f;
    #pragma unroll 8
    for (int c = 0; c < CH; c++) s = fmaf(f[(size_t)c*HW], wg[c], s);
    s = fmaxf(s, 0.f);
    g_m[p] = s;
    __shared__ float sm[256];
    sm[t] = s; __syncthreads();
    for (int st = 128; st; st >>= 1){
        if (t < st) sm[t] = fmaxf(sm[t], sm[t+st]);
        __syncthreads();
    }
    if (!t) g_rmax[blockIdx.x] = sm[0];
}

// finalize per-image scale: 1 block x 64 threads (16 partials per image)
__global__ void k_scale(){
    int t = threadIdx.x;          // 0..63
    int n = t >> 4, i = t & 15;
    __shared__ float sm[64];
    sm[t] = g_rmax[t]; __syncthreads();
    for (int st = 8; st; st >>= 1){
        if (i < st) sm[t] = fmaxf(sm[t], sm[t+st]);
        __syncthreads();
    }
    if (!i) g_scale[n] = 1.f / fmaxf(sm[t], 1.f);
}

// ---------------------------------------------------------------------------
// 2) channel sums (for pred)  grid 1024 (n*C+c) x 256
// ---------------------------------------------------------------------------
__global__ void k_chansum(const float* __restrict__ feats){
    int nc = blockIdx.x;
    const float* f = feats + (size_t)nc*HW;
    float s = 0.f;
    for (int i = threadIdx.x; i < HW; i += 256) s += f[i];
    __shared__ float sm[256];
    sm[threadIdx.x] = s; __syncthreads();
    for (int st = 128; st; st >>= 1){
        if (threadIdx.x < st) sm[threadIdx.x] += sm[threadIdx.x+st];
        __syncthreads();
    }
    if (!threadIdx.x) g_chansum[nc] = sm[0];
}

// weighted channel sums Σ feats * wsum[head(c)]  (for pred_r)
__global__ void k_wchansum(const float* __restrict__ feats){
    int nc = blockIdx.x;
    int n = nc >> 8, c = nc & 255, a = c >> 6;
    const float* f  = feats + (size_t)nc*HW;
    const float* ws = g_wsum + a*LPIX + n*HW;
    float s = 0.f;
    for (int i = threadIdx.x; i < HW; i += 256) s = fmaf(f[i], ws[i], s);
    __shared__ float sm[256];
    sm[threadIdx.x] = s; __syncthreads();
    for (int st = 128; st; st >>= 1){
        if (threadIdx.x < st) sm[threadIdx.x] += sm[threadIdx.x+st];
        __syncthreads();
    }
    if (!threadIdx.x) g_S[nc] = sm[0];
}

// pred / pred_r : 80 dots of length 256 ; USE_S picks the accumulator source
template<bool USE_S>
__global__ void k_pred(const float* __restrict__ wg, float* __restrict__ outp){
    int t = threadIdx.x;
    if (t >= NB*NCLS) return;
    int n = t / NCLS, k = t % NCLS;
    const float* cs = (USE_S ? g_S : g_chansum) + n*CH;
    const float* w  = wg + k*CH;
    float s = 0.f;
    for (int c = 0; c < CH; c++) s = fmaf(w[c], cs[c], s);
    outp[t] = s * (1.f/HW);
}

// ---------------------------------------------------------------------------
// 3) window attention (shared by infusion & diffusion)
//    score[a,k,p] = sum_{c in head a} Wt[c, p+off_k] * Ct[c, p]   (zero-pad)
//    softmax over k ; diffusion additionally multiplies by the mask at p.
//    grid 256 x 256 : thread = (head = tid>>6, pixel = blk*64 + (tid&63))
// ---------------------------------------------------------------------------
template<int KS, int DIL, bool MASKED>
__global__ void k_att(const float* __restrict__ Wt, const float* __restrict__ Ct){
    constexpr int K2 = KS*KS;
    int t = threadIdx.x;
    int a = t >> 6;
    int p = blockIdx.x*64 + (t & 63);
    int n = p >> 12, hw = p & 4095, h = hw >> 6, w = hw & 63;

    int off[K2]; float acc[K2];
    #pragma unroll
    for (int fi = 0; fi < KS; fi++)
        #pragma unroll
        for (int fj = 0; fj < KS; fj++){
            int q  = fi*KS + fj;
            int hh = h + (fi - KS/2)*DIL, ww = w + (fj - KS/2)*DIL;
            off[q] = ((unsigned)hh < 64u && (unsigned)ww < 64u) ? hh*64 + ww : -1;
            acc[q] = 0.f;   // OOB windows contribute exactly 0 (zero padding)
        }
    const float* wb = Wt + (size_t)(n*CH + a*64)*HW;
    const float* cb = Ct + (size_t)(n*CH + a*64)*HW + hw;
    for (int c = 0; c < 64; c++){
        float cv = cb[(size_t)c*HW];
        const float* wr = wb + (size_t)c*HW;
        #pragma unroll
        for (int q = 0; q < K2; q++)
            if (off[q] >= 0) acc[q] = fmaf(wr[off[q]], cv, acc[q]);
    }
    float mx = acc[0];
    #pragma unroll
    for (int q = 1; q < K2; q++) mx = fmaxf(mx, acc[q]);
    float ssum = 0.f;
    #pragma unroll
    for (int q = 0; q < K2; q++){ acc[q] = expf(acc[q]-mx); ssum += acc[q]; }
    float inv = 1.f / ssum;
    if (MASKED) inv *= g_m[p]*g_scale[n];
    float* att = MASKED ? g_attd : g_atti;
    #pragma unroll
    for (int q = 0; q < K2; q++) att[(size_t)(a*K2+q)*LPIX + p] = acc[q]*inv;
}

// scatter-weight sums for pred_r:  wsum[a,p] = Σ_k att_i[a,k,p-off_k]
__global__ void k_wsum(){
    int idx = blockIdx.x*256 + threadIdx.x;   // a*LPIX + p
    int a = idx >> 14, p = idx & 16383;
    int n = p >> 12, hw = p & 4095, h = hw >> 6, w = hw & 63;
    float s = 0.f;
    #pragma unroll
    for (int fi = 0; fi < 5; fi++)
        #pragma unroll
        for (int fj = 0; fj < 5; fj++){
            int q  = fi*5 + fj;
            int hh = h - (fi-2)*3, ww = w - (fj-2)*3;
            if ((unsigned)hh < 64u && (unsigned)ww < 64u)
                s += g_atti[(size_t)(a*25+q)*LPIX + (n<<12) + hh*64 + ww];
        }
    g_wsum[idx] = s;
}

// ---------------------------------------------------------------------------
// 4) build conv input x = [feats*mask  ||  feats_d]   grid 64 x 256
//    feats_d(p) = Σ_k feats(p-off_k)*att_d[a,k,p-off_k]   (col2im as gather)
// ---------------------------------------------------------------------------
__global__ void k_build_x(const float* __restrict__ feats){
    int t = threadIdx.x;
    int p = blockIdx.x*256 + t;
    int n = p >> 12, hw = p & 4095, h = hw >> 6, w = hw & 63;
    float mv = g_m[p]*g_scale[n];
    const float* f  = feats + (size_t)n*CH*HW + hw;
    float*       x0 = g_x   + (size_t)n*512*HW + hw;
    int src[9];
    #pragma unroll
    for (int fi = 0; fi < 3; fi++)
        #pragma unroll
        for (int fj = 0; fj < 3; fj++){
            int q  = fi*3 + fj;
            int hh = h - (fi-1)*6, ww = w - (fj-1)*6;
            src[q] = ((unsigned)hh < 64u && (unsigned)ww < 64u) ? hh*64 + ww : -1;
        }
    #pragma unroll 4
    for (int c = 0; c < CH; c++) x0[(size_t)c*HW] = f[(size_t)c*HW]*mv;
    for (int a = 0; a < 4; a++){
        float av[9];
        #pragma unroll
        for (int q = 0; q < 9; q++)
            av[q] = (src[q] >= 0) ? g_attd[(size_t)(a*9+q)*LPIX + (n<<12) + src[q]] : 0.f;
        const float* fa = feats + (size_t)(n*CH + a*64)*HW;
        #pragma unroll 2
        for (int cc = 0; cc < 64; cc++){
            const float* fc = fa + (size_t)cc*HW;
            float s = 0.f;
            #pragma unroll
            for (int q = 0; q < 9; q++)
                if (src[q] >= 0) s = fmaf(fc[src[q]], av[q], s);
            x0[(size_t)(256 + a*64 + cc)*HW] = s;
        }
    }
}

// ---------------------------------------------------------------------------
// 5) weight transpose [co][ci][kh][kw] -> [kh][ci][kw][co]   (coalesced writes)
// ---------------------------------------------------------------------------
__global__ void k_wtrans(const float* __restrict__ w){
    int idx = blockIdx.x*256 + threadIdx.x;   // = ((kh*512+ci)*3+kw)*256+co
    int co = idx & 255;
    int r  = idx >> 8;
    int kw = r % 3; r /= 3;
    int ci = r & 511; int kh = r >> 9;
    g_wT[idx] = w[(((size_t)co*512 + ci)*3 + kh)*3 + kw];
}

// ---------------------------------------------------------------------------
// 6) 3x3 conv, 512 -> 256 ch, implicit GEMM with packed f32x2 FFMA
//    grid (2, 256): blockIdx.x = 128-co tile, blockIdx.y = n*64 + h (one row)
//    block 256 thr; thread = (tw = tid&15 -> 4 w, tc = tid>>4 -> 8 co as pairs)
// ---------------------------------------------------------------------------
__global__ void __launch_bounds__(256,2)
k_conv(const float* __restrict__ bias, float* __restrict__ out){
    __shared__ float sW[16*3*128];   // [ci-chunk][kw][co]  24.6 KB
    __shared__ float sX[16*66];      // [ci-chunk][w+halo]   4.2 KB
    int tid = threadIdx.x;
    int tw = tid & 15, tc = tid >> 4;
    int co0 = blockIdx.x * 128;
    int nh = blockIdx.y; int n = nh >> 6, h = nh & 63;

    ull acc[4][4];                   // [co-pair][w] packed (co_even, co_odd)
    #pragma unroll
    for (int p4 = 0; p4 < 4; p4++)
        #pragma unroll
        for (int j = 0; j < 4; j++) acc[p4][j] = 0ull;

    const float* xn = g_x + (size_t)n*512*HW;
    for (int kh = 0; kh < 3; kh++){
        int r = h + kh - 1;
        if ((unsigned)r >= 64u) continue;          // zero padding row (uniform)
        for (int ci0 = 0; ci0 < 512; ci0 += 16){
            for (int idx = tid; idx < 16*66; idx += 256){
                int i = idx/66; int m = idx - i*66; int wv = m - 1;
                sX[idx] = ((unsigned)wv < 64u)
                        ? xn[(size_t)(ci0+i)*HW + r*64 + wv] : 0.f;
            }
            const float* wsrc = g_wT + ((size_t)(kh*512 + ci0))*3*256 + co0;
            for (int idx = tid; idx < 16*3*128; idx += 256){
                int c = idx & 127; int rr = idx >> 7;   // rr = i*3+kw
                sW[idx] = wsrc[(size_t)rr*256 + c];
            }
            __syncthreads();
            #pragma unroll 4
            for (int i = 0; i < 16; i++){
                ull bb[6];
                #pragma unroll
                for (int j = 0; j < 6; j++){
                    float bv = sX[i*66 + tw*4 + j];
                    bb[j] = pk2(bv, bv);
                }
                #pragma unroll
                for (int kw = 0; kw < 3; kw++){
                    const float* wr = &sW[(i*3+kw)*128 + tc*8];
                    ull a0 = *(const ull*)(wr+0);
                    ull a1 = *(const ull*)(wr+2);
                    ull a2 = *(const ull*)(wr+4);
                    ull a3 = *(const ull*)(wr+6);
                    #pragma unroll
                    for (int j = 0; j < 4; j++){
                        ffma2(acc[0][j], a0, bb[kw+j]);
                        ffma2(acc[1][j], a1, bb[kw+j]);
                        ffma2(acc[2][j], a2, bb[kw+j]);
                        ffma2(acc[3][j], a3, bb[kw+j]);
                    }
                }
            }
            __syncthreads();
        }
    }
    #pragma unroll
    for (int p4 = 0; p4 < 4; p4++){
        int co = co0 + tc*8 + 2*p4;
        float b0 = bias[co], b1 = bias[co+1];
        float4 v0, v1; float lo, hi;
        upk2(acc[p4][0], lo, hi); v0.x = lo+b0; v1.x = hi+b1;
        upk2(acc[p4][1], lo, hi); v0.y = lo+b0; v1.y = hi+b1;
        upk2(acc[p4][2], lo, hi); v0.z = lo+b0; v1.z = hi+b1;
        upk2(acc[p4][3], lo, hi); v0.w = lo+b0; v1.w = hi+b1;
        float* o = out + ((size_t)(n*CH + co)*64 + h)*64 + tw*4;
        *(float4*)o        = v0;
        *(float4*)(o + HW) = v1;
    }
}

// ---------------------------------------------------------------------------
extern "C" void kernel_launch(void* const* d_in, const int* in_sizes, int n_in,
                              void* d_out, int out_size){
    const float* feats   = (const float*)d_in[0];
    const float* Kin     = (const float*)d_in[1];
    const float* Qin     = (const float*)d_in[2];
    const float* w_gap   = (const float*)d_in[3];
    const float* w_gap_r = (const float*)d_in[4];
    const float* conv_w  = (const float*)d_in[5];
    const float* conv_b  = (const float*)d_in[6];
    const int*   label   = (const int*)d_in[7];
    float* out = (float*)d_out;

    // weight transpose for coalesced conv loads
    k_wtrans<<<4608,256>>>(conv_w);

    // mask + pred
    k_mask<<<64,256>>>(feats, w_gap, label);
    k_scale<<<1,64>>>();
    k_chansum<<<1024,256>>>(feats);
    k_pred<false><<<1,128>>>(w_gap, out + 4194304);

    // infusion -> pred_r  (Bayes swaps K/Q: windows from Q, centers from K)
    k_att<5,3,false><<<256,256>>>(Qin, Kin);
    k_wsum<<<256,256>>>();
    k_wchansum<<<1024,256>>>(feats);
    k_pred<true><<<1,128>>>(w_gap_r, out + 4194384);

    // diffusion (windows from K, centers from Q) + conv input assembly
    k_att<3,6,true><<<256,256>>>(Kin, Qin);
    k_build_x<<<64,256>>>(feats);

    // the big one
    k_conv<<<dim3(2,256),256>>>(conv_b, out);
}

// round 6
// speedup vs baseline: 2.1029x; 2.1029x over previous
#include <cuda_runtime.h>

// ---------------------------------------------------------------------------
// Bayes_4294967296643 : full pipeline; conv via mma.sync tf32 (sm_100-safe)
// ---------------------------------------------------------------------------

#define NB    4
#define CH    256
#define HW    4096
#define LPIX  16384
#define NCLS  20

typedef unsigned int u32;

// ---- scratch (device globals; no allocation allowed) ----------------------
__device__ float g_m[NB*HW];          // relu'd label heatmap (mask numerator)
__device__ float g_rmax[64];
__device__ float g_scale[NB];
__device__ float g_chansum[NB*CH];
__device__ float g_S[NB*CH];
__device__ float g_atti[4*25*LPIX];   // infusion attention  [a][k][p]
__device__ float g_attd[4*9*LPIX];    // diffusion attention [a][k][p]
__device__ float g_wsum[4*LPIX];
__device__ float g_wA[9*256*512];     // weights [tap][co][ci], tf32-rounded
__device__ float g_x[NB*512*HW];      // conv input, tf32-rounded

// cvt.rna.tf32.f32 needs a .b32 destination register
__device__ __forceinline__ float to_tf32(float x){
    u32 r; asm("cvt.rna.tf32.f32 %0, %1;" : "=r"(r) : "f"(x));
    return __uint_as_float(r);
}

// ---------------------------------------------------------------------------
// 1) mask numerator + per-block max
// ---------------------------------------------------------------------------
__global__ void k_mask(const float* __restrict__ feats,
                       const float* __restrict__ wgap,
                       const int*   __restrict__ label){
    int t = threadIdx.x;
    int p = blockIdx.x*256 + t;
    int n = p >> 12, hw = p & 4095;
    int lab = label[n];
    const float* f  = feats + (size_t)n*CH*HW + hw;
    const float* wg = wgap + lab*CH;
    float s = 0.f;
    #pragma unroll 8
    for (int c = 0; c < CH; c++) s = fmaf(f[(size_t)c*HW], wg[c], s);
    s = fmaxf(s, 0.f);
    g_m[p] = s;
    __shared__ float sm[256];
    sm[t] = s; __syncthreads();
    for (int st = 128; st; st >>= 1){
        if (t < st) sm[t] = fmaxf(sm[t], sm[t+st]);
        __syncthreads();
    }
    if (!t) g_rmax[blockIdx.x] = sm[0];
}

__global__ void k_scale(){
    int t = threadIdx.x;          // 0..63
    int n = t >> 4, i = t & 15;
    __shared__ float sm[64];
    sm[t] = g_rmax[t]; __syncthreads();
    for (int st = 8; st; st >>= 1){
        if (i < st) sm[t] = fmaxf(sm[t], sm[t+st]);
        __syncthreads();
    }
    if (!i) g_scale[n] = 1.f / fmaxf(sm[t], 1.f);
}

// ---------------------------------------------------------------------------
// 2) channel sums (float4)
// ---------------------------------------------------------------------------
__global__ void k_chansum(const float* __restrict__ feats){
    int nc = blockIdx.x;
    const float4* f = (const float4*)(feats + (size_t)nc*HW);
    float s = 0.f;
    for (int i = threadIdx.x; i < HW/4; i += 256){
        float4 v = f[i]; s += (v.x+v.y)+(v.z+v.w);
    }
    __shared__ float sm[256];
    sm[threadIdx.x] = s; __syncthreads();
    for (int st = 128; st; st >>= 1){
        if (threadIdx.x < st) sm[threadIdx.x] += sm[threadIdx.x+st];
        __syncthreads();
    }
    if (!threadIdx.x) g_chansum[nc] = sm[0];
}

__global__ void k_wchansum(const float* __restrict__ feats){
    int nc = blockIdx.x;
    int n = nc >> 8, c = nc & 255, a = c >> 6;
    const float4* f  = (const float4*)(feats + (size_t)nc*HW);
    const float4* ws = (const float4*)(g_wsum + a*LPIX + n*HW);
    float s = 0.f;
    for (int i = threadIdx.x; i < HW/4; i += 256){
        float4 v = f[i], u = ws[i];
        s = fmaf(v.x,u.x, fmaf(v.y,u.y, fmaf(v.z,u.z, fmaf(v.w,u.w, s))));
    }
    __shared__ float sm[256];
    sm[threadIdx.x] = s; __syncthreads();
    for (int st = 128; st; st >>= 1){
        if (threadIdx.x < st) sm[threadIdx.x] += sm[threadIdx.x+st];
        __syncthreads();
    }
    if (!threadIdx.x) g_S[nc] = sm[0];
}

template<bool USE_S>
__global__ void k_pred(const float* __restrict__ wg, float* __restrict__ outp){
    int t = threadIdx.x;
    if (t >= NB*NCLS) return;
    int n = t / NCLS, k = t % NCLS;
    const float* cs = (USE_S ? g_S : g_chansum) + n*CH;
    const float* w  = wg + k*CH;
    float s = 0.f;
    for (int c = 0; c < CH; c++) s = fmaf(w[c], cs[c], s);
    outp[t] = s * (1.f/HW);
}

// ---------------------------------------------------------------------------
// 3) window attention (infusion / diffusion)
// ---------------------------------------------------------------------------
template<int KS, int DIL, bool MASKED>
__global__ void k_att(const float* __restrict__ Wt, const float* __restrict__ Ct){
    constexpr int K2 = KS*KS;
    int t = threadIdx.x;
    int a = t >> 6;
    int p = blockIdx.x*64 + (t & 63);
    int n = p >> 12, hw = p & 4095, h = hw >> 6, w = hw & 63;

    int off[K2]; float acc[K2];
    #pragma unroll
    for (int fi = 0; fi < KS; fi++)
        #pragma unroll
        for (int fj = 0; fj < KS; fj++){
            int q  = fi*KS + fj;
            int hh = h + (fi - KS/2)*DIL, ww = w + (fj - KS/2)*DIL;
            off[q] = ((unsigned)hh < 64u && (unsigned)ww < 64u) ? hh*64 + ww : -1;
            acc[q] = 0.f;
        }
    const float* wb = Wt + (size_t)(n*CH + a*64)*HW;
    const float* cb = Ct + (size_t)(n*CH + a*64)*HW + hw;
    for (int c = 0; c < 64; c++){
        float cv = cb[(size_t)c*HW];
        const float* wr = wb + (size_t)c*HW;
        #pragma unroll
        for (int q = 0; q < K2; q++)
            if (off[q] >= 0) acc[q] = fmaf(wr[off[q]], cv, acc[q]);
    }
    float mx = acc[0];
    #pragma unroll
    for (int q = 1; q < K2; q++) mx = fmaxf(mx, acc[q]);
    float ssum = 0.f;
    #pragma unroll
    for (int q = 0; q < K2; q++){ acc[q] = expf(acc[q]-mx); ssum += acc[q]; }
    float inv = 1.f / ssum;
    if (MASKED) inv *= g_m[p]*g_scale[n];
    float* att = MASKED ? g_attd : g_atti;
    #pragma unroll
    for (int q = 0; q < K2; q++) att[(size_t)(a*K2+q)*LPIX + p] = acc[q]*inv;
}

__global__ void k_wsum(){
    int idx = blockIdx.x*256 + threadIdx.x;   // a*LPIX + p
    int a = idx >> 14, p = idx & 16383;
    int n = p >> 12, hw = p & 4095, h = hw >> 6, w = hw & 63;
    float s = 0.f;
    #pragma unroll
    for (int fi = 0; fi < 5; fi++)
        #pragma unroll
        for (int fj = 0; fj < 5; fj++){
            int q  = fi*5 + fj;
            int hh = h - (fi-2)*3, ww = w - (fj-2)*3;
            if ((unsigned)hh < 64u && (unsigned)ww < 64u)
                s += g_atti[(size_t)(a*25+q)*LPIX + (n<<12) + hh*64 + ww];
        }
    g_wsum[idx] = s;
}

// ---------------------------------------------------------------------------
// 4) build conv input x = [feats*mask || feats_d], tf32-rounded
// ---------------------------------------------------------------------------
__global__ void k_build_x(const float* __restrict__ feats){
    int t = threadIdx.x;
    int p = blockIdx.x*256 + t;
    int n = p >> 12, hw = p & 4095, h = hw >> 6, w = hw & 63;
    float mv = g_m[p]*g_scale[n];
    const float* f  = feats + (size_t)n*CH*HW + hw;
    float*       x0 = g_x   + (size_t)n*512*HW + hw;
    int src[9];
    #pragma unroll
    for (int fi = 0; fi < 3; fi++)
        #pragma unroll
        for (int fj = 0; fj < 3; fj++){
            int q  = fi*3 + fj;
            int hh = h - (fi-1)*6, ww = w - (fj-1)*6;
            src[q] = ((unsigned)hh < 64u && (unsigned)ww < 64u) ? hh*64 + ww : -1;
        }
    #pragma unroll 4
    for (int c = 0; c < CH; c++) x0[(size_t)c*HW] = to_tf32(f[(size_t)c*HW]*mv);
    for (int a = 0; a < 4; a++){
        float av[9];
        #pragma unroll
        for (int q = 0; q < 9; q++)
            av[q] = (src[q] >= 0) ? g_attd[(size_t)(a*9+q)*LPIX + (n<<12) + src[q]] : 0.f;
        const float* fa = feats + (size_t)(n*CH + a*64)*HW;
        #pragma unroll 2
        for (int cc = 0; cc < 64; cc++){
            const float* fc = fa + (size_t)cc*HW;
            float s = 0.f;
            #pragma unroll
            for (int q = 0; q < 9; q++)
                if (src[q] >= 0) s = fmaf(fc[src[q]], av[q], s);
            x0[(size_t)(256 + a*64 + cc)*HW] = to_tf32(s);
        }
    }
}

// ---------------------------------------------------------------------------
// 5) weight prep: conv_w[co][ci][kh][kw] -> g_wA[tap][co][ci] (tf32)
// ---------------------------------------------------------------------------
__global__ void k_wprep(const float* __restrict__ w){
    int idx = blockIdx.x*256 + threadIdx.x;   // ((tap*256+co)*512+ci)
    int ci = idx & 511;
    int r  = idx >> 9;
    int co = r & 255; int tap = r >> 8;
    int kh = tap/3, kw = tap - kh*3;
    g_wA[idx] = to_tf32(w[(((size_t)co*512 + ci)*3 + kh)*3 + kw]);
}

// ---------------------------------------------------------------------------
// 6) conv as implicit GEMM on mma.sync m16n8k8 tf32
//    grid 256: blk = n*64 + cohalf*32 + ptile  (FIX: cover all 256 co)
//    block tile 128co x 128px; 8 warps (2 co x 4 px); warp 64co x 32px.
//    K streamed: 144 chunks of 32 ci (9 taps x 16), reg-prefetch dbl buffer.
// ---------------------------------------------------------------------------
#define ASTR 36
#define BSTR 132

__global__ void __launch_bounds__(256,1)
k_conv_mma(const float* __restrict__ bias, float* __restrict__ out){
    __shared__ float sA[128*ASTR];   // [co][ci]  18.4 KB
    __shared__ float sB[32*BSTR];    // [ci][px]  16.9 KB
    int tid  = threadIdx.x;
    int wid  = tid >> 5, lane = tid & 31;
    int gid  = lane >> 2, tig = lane & 3;
    int wco  = wid & 1, wpx = wid >> 1;
    int blk  = blockIdx.x;
    int n    = blk >> 6;
    int cohalf = (blk >> 5) & 1;
    int p0   = (blk & 31) * 128;

    const float* xs = g_x + (size_t)n*512*HW;

    float acc[4][4][4];
    #pragma unroll
    for (int mi = 0; mi < 4; mi++)
        #pragma unroll
        for (int ni = 0; ni < 4; ni++)
            #pragma unroll
            for (int r = 0; r < 4; r++) acc[mi][ni][r] = 0.f;

    float ra[16], rb[16];
    // A: idx=e*256+tid -> co=idx>>5, ci=idx&31 ; B: ci=idx>>7, pl=idx&127
    #define LOAD_CHUNK(I) { \
        int tap = (I) >> 4, ci0 = ((I) & 15) * 32; \
        int dh = tap/3 - 1, dw = tap - (tap/3)*3 - 1; \
        const float* wsrc = g_wA + ((size_t)(tap*256 + cohalf*128))*512 + ci0; \
        _Pragma("unroll") \
        for (int e = 0; e < 16; e++){ \
            int idx = e*256 + tid; \
            ra[e] = wsrc[(size_t)(idx>>5)*512 + (idx&31)]; \
            int ci = idx >> 7, pl = idx & 127; \
            int p = p0 + pl; \
            int hh = (p>>6) + dh, ww = (p&63) + dw; \
            rb[e] = ((unsigned)hh < 64u && (unsigned)ww < 64u) \
                  ? xs[(size_t)(ci0+ci)*HW + (hh<<6) + ww] : 0.f; \
        } }
    #define STORE_CHUNK() { \
        _Pragma("unroll") \
        for (int e = 0; e < 16; e++){ \
            int idx = e*256 + tid; \
            sA[(idx>>5)*ASTR + (idx&31)] = ra[e]; \
            sB[(idx>>7)*BSTR + (idx&127)] = rb[e]; \
        } }

    LOAD_CHUNK(0);
    STORE_CHUNK();
    __syncthreads();

    for (int i = 0; i < 144; i++){
        if (i < 143) LOAD_CHUNK(i+1);

        const float* Abase = sA + (wco*64 + gid)*ASTR;
        const float* Bbase = sB + tig*BSTR + wpx*32 + gid;
        #pragma unroll
        for (int ks = 0; ks < 4; ks++){
            u32 af[4][4], bf[4][2];
            #pragma unroll
            for (int mi = 0; mi < 4; mi++){
                const float* ap = Abase + mi*16*ASTR + ks*8 + tig;
                af[mi][0] = __float_as_uint(ap[0]);
                af[mi][1] = __float_as_uint(ap[8*ASTR]);
                af[mi][2] = __float_as_uint(ap[4]);
                af[mi][3] = __float_as_uint(ap[8*ASTR+4]);
            }
            #pragma unroll
            for (int ni = 0; ni < 4; ni++){
                const float* bp = Bbase + ks*8*BSTR + ni*8;
                bf[ni][0] = __float_as_uint(bp[0]);
                bf[ni][1] = __float_as_uint(bp[4*BSTR]);
            }
            #pragma unroll
            for (int mi = 0; mi < 4; mi++)
                #pragma unroll
                for (int ni = 0; ni < 4; ni++){
                    float* d = acc[mi][ni];
                    asm volatile(
                        "mma.sync.aligned.m16n8k8.row.col.f32.tf32.tf32.f32 "
                        "{%0,%1,%2,%3}, {%4,%5,%6,%7}, {%8,%9}, {%0,%1,%2,%3};"
                        : "+f"(d[0]), "+f"(d[1]), "+f"(d[2]), "+f"(d[3])
                        : "r"(af[mi][0]), "r"(af[mi][1]), "r"(af[mi][2]),
                          "r"(af[mi][3]), "r"(bf[ni][0]), "r"(bf[ni][1]));
                }
        }
        __syncthreads();
        if (i < 143){
            STORE_CHUNK();
            __syncthreads();
        }
    }

    // epilogue: acc[mi][ni] row0=co, row1=co+8 ; cols 2*tig, 2*tig+1
    #pragma unroll
    for (int mi = 0; mi < 4; mi++){
        int co = cohalf*128 + wco*64 + mi*16 + gid;
        float bv0 = bias[co], bv8 = bias[co+8];
        float* o0 = out + ((size_t)(n*CH + co))*HW + p0;
        #pragma unroll
        for (int ni = 0; ni < 4; ni++){
            int px = wpx*32 + ni*8 + 2*tig;
            float2 v0 = { acc[mi][ni][0] + bv0, acc[mi][ni][1] + bv0 };
            float2 v1 = { acc[mi][ni][2] + bv8, acc[mi][ni][3] + bv8 };
            *(float2*)(o0 + px)        = v0;
            *(float2*)(o0 + 8*HW + px) = v1;
        }
    }
}

// ---------------------------------------------------------------------------
extern "C" void kernel_launch(void* const* d_in, const int* in_sizes, int n_in,
                              void* d_out, int out_size){
    const float* feats   = (const float*)d_in[0];
    const float* Kin     = (const float*)d_in[1];
    const float* Qin     = (const float*)d_in[2];
    const float* w_gap   = (const float*)d_in[3];
    const float* w_gap_r = (const float*)d_in[4];
    const float* conv_w  = (const float*)d_in[5];
    const float* conv_b  = (const float*)d_in[6];
    const int*   label   = (const int*)d_in[7];
    float* out = (float*)d_out;

    // order: k_conv_mma is launch index 5 so ncu (-s 5 -c 1) profiles it
    k_wprep<<<4608,256>>>(conv_w);                  // 0
    k_mask<<<64,256>>>(feats, w_gap, label);        // 1
    k_scale<<<1,64>>>();                            // 2
    k_att<3,6,true><<<256,256>>>(Kin, Qin);         // 3  diffusion attention
    k_build_x<<<64,256>>>(feats);                   // 4
    k_conv_mma<<<256,256>>>(conv_b, out);           // 5  <-- profiled

    k_chansum<<<1024,256>>>(feats);
    k_pred<false><<<1,128>>>(w_gap, out + 4194304);

    k_att<5,3,false><<<256,256>>>(Qin, Kin);        // infusion attention
    k_wsum<<<256,256>>>();
    k_wchansum<<<1024,256>>>(feats);
    k_pred<true><<<1,128>>>(w_gap_r, out + 4194384);
}